// round 4
// baseline (speedup 1.0000x reference)
#include <cuda_runtime.h>
#include <math.h>

#define DD  96
#define PLN (DD*DD)
#define VOL (DD*DD*DD)
#define NC  16

#define BUFROW 200          // padded row stride (floats) for 192-voxel tile
#define OFF_BUF 0
#define OFF_WPC 12800       // u64[648]  (1296 floats)
#define OFF_W1T 14096       // 48*64
#define OFF_W2T 17168       // 64*64
#define OFF_W3T 21264       // 64*16
#define OFF_BPP 22288       // u64[24]   (48 floats)
#define OFF_B1  22336
#define OFF_B2  22400
#define OFF_B3  22464
#define OFF_RED 22480
#define SMEM_FLOATS 22504
#define SMEM_BYTES (SMEM_FLOATS*4)

__device__ __align__(16) float g_A[NC*VOL];
__device__ __align__(16) float g_B[NC*VOL];
__device__ float    g_alive0[VOL];
__device__ unsigned g_maxPre[5];
__device__ unsigned g_maxPost[4];

__device__ __forceinline__ unsigned encf(float f) {
    unsigned u = __float_as_uint(f);
    return (u & 0x80000000u) ? ~u : (u | 0x80000000u);
}
__device__ __forceinline__ float decf(unsigned e) {
    return __uint_as_float((e & 0x80000000u) ? (e ^ 0x80000000u) : ~e);
}
__device__ __forceinline__ float tanh_fast(float x) {
    float y; asm("tanh.approx.f32 %0, %1;" : "=f"(y) : "f"(x)); return y;
}

typedef unsigned long long u64t;
__device__ __forceinline__ u64t pack2(float lo, float hi) {
    u64t r; asm("mov.b64 %0, {%1, %2};" : "=l"(r) : "f"(lo), "f"(hi)); return r;
}
__device__ __forceinline__ void unpack2(u64t v, float& lo, float& hi) {
    asm("mov.b64 {%0, %1}, %2;" : "=f"(lo), "=f"(hi) : "l"(v));
}
__device__ __forceinline__ u64t ffma2(u64t a, u64t b, u64t c) {
    u64t d; asm("fma.rn.f32x2 %0, %1, %2, %3;" : "=l"(d) : "l"(a), "l"(b), "l"(c)); return d;
}
__device__ __forceinline__ u64t fadd2(u64t a, u64t b) {
    u64t d; asm("add.rn.f32x2 %0, %1, %2;" : "=l"(d) : "l"(a), "l"(b)); return d;
}

__global__ void init_kernel() {
    int t = threadIdx.x;
    if (t < 5) g_maxPre[t]  = 0x007FFFFFu;
    if (t < 4) g_maxPost[t] = 0x007FFFFFu;
}

__global__ void reduce_ch3_kernel(const float* __restrict__ p) {
    float m = -INFINITY;
    for (int i = blockIdx.x * blockDim.x + threadIdx.x; i < VOL; i += gridDim.x * blockDim.x)
        m = fmaxf(m, p[i]);
    #pragma unroll
    for (int s = 16; s > 0; s >>= 1) m = fmaxf(m, __shfl_xor_sync(0xffffffffu, m, s));
    __shared__ float sm[8];
    if ((threadIdx.x & 31) == 0) sm[threadIdx.x >> 5] = m;
    __syncthreads();
    if (threadIdx.x == 0) {
        int nw = (blockDim.x + 31) / 32;
        float mm = sm[0];
        for (int i = 1; i < nw; i++) mm = fmaxf(mm, sm[i]);
        atomicMax(&g_maxPre[0], encf(mm));
    }
}

// perm: logical conv output i = c*3+j -> slot s = 2*((c/2)*3 + j) + (c%2)
__device__ __host__ __forceinline__ int perm48(int i) {
    int c = i / 3, j = i % 3;
    return 2 * ((c / 2) * 3 + j) + (c % 2);
}

__global__ __launch_bounds__(192, 2) void update_kernel(
    const float* __restrict__ xin,
    const float* __restrict__ w_perc, const float* __restrict__ b_perc,
    const float* __restrict__ w1, const float* __restrict__ b1,
    const float* __restrict__ w2, const float* __restrict__ b2,
    const float* __restrict__ w3, const float* __restrict__ b3,
    int step)
{
    const float* cur = (step == 0) ? xin : (const float*)g_A;

    extern __shared__ float smem[];
    float* buf    = smem + OFF_BUF;            // [64][BUFROW] activations
    u64t*  s_wpc  = (u64t*)(smem + OFF_WPC);   // conv weight pairs
    float* s_w1t  = smem + OFF_W1T;            // [slot(i)][o]
    float* s_w2t  = smem + OFF_W2T;            // [i][o]
    float* s_w3t  = smem + OFF_W3T;            // [i][o]
    u64t*  s_bpp  = (u64t*)(smem + OFF_BPP);
    float* s_b1   = smem + OFF_B1;
    float* s_b2   = smem + OFF_B2;
    float* s_b3   = smem + OFF_B3;
    float* s_red  = smem + OFF_RED;

    const int t = threadIdx.x;

    // ---- stage weights ----
    for (int idx = t; idx < 8*27*3; idx += 192) {
        int c2 = idx / 81, r = idx % 81, k = r / 3, j = r % 3;
        s_wpc[idx] = pack2(w_perc[((2*c2)*3 + j)*27 + k], w_perc[((2*c2+1)*3 + j)*27 + k]);
    }
    for (int idx = t; idx < 48*64; idx += 192) { int o = idx/48, i = idx%48; s_w1t[perm48(i)*64 + o] = w1[idx]; }
    for (int idx = t; idx < 64*64; idx += 192) { int o = idx/64, i = idx%64; s_w2t[i*64 + o] = w2[idx]; }
    for (int idx = t; idx < 16*64; idx += 192) { int o = idx/64, i = idx%64; s_w3t[i*16 + o] = w3[idx]; }
    if (t < 64) { s_b1[t] = b1[t]; s_b2[t] = b2[t]; }
    if (t < 16) s_b3[t] = b3[t];
    if (t >= 64 && t < 88) {
        int p = t - 64, c2 = p / 3, j = p % 3;
        s_bpp[p] = pack2(b_perc[(2*c2)*3 + j], b_perc[(2*c2+1)*3 + j]);
    }
    __syncthreads();

    // ---- geometry ----
    const int lin0 = blockIdx.x * 192;
    const int d  = blockIdx.x / 48;
    const int h0 = (blockIdx.x % 48) * 2;
    const int w  = t % 96;
    const int hh = h0 + t / 96;
    const int pos = lin0 + t;

    bool vD[3] = { d > 0, true, d < DD-1 };
    bool vH[3] = { hh > 0, true, hh < DD-1 };
    bool vW[3] = { w > 0, true, w < DD-1 };
    bool v27[27];
    #pragma unroll
    for (int kd = 0; kd < 3; kd++)
        #pragma unroll
        for (int kh = 0; kh < 3; kh++)
            #pragma unroll
            for (int kw = 0; kw < 3; kw++)
                v27[(kd*3+kh)*3+kw] = vD[kd] && vH[kh] && vW[kw];

    // ---- depthwise conv: rolling pair accumulators, store f to buf ----
    float alive0v = -INFINITY;
    {
        const float* b0 = cur + pos;
        for (int c2 = 0; c2 < 8; c2++) {
            u64t f0 = s_bpp[c2*3+0], f1 = s_bpp[c2*3+1], f2 = s_bpp[c2*3+2];
            const u64t* wp = &s_wpc[c2*27*3];
            #pragma unroll
            for (int kd = 0; kd < 3; kd++)
                #pragma unroll
                for (int kh = 0; kh < 3; kh++)
                    #pragma unroll
                    for (int kw = 0; kw < 3; kw++) {
                        const int k = (kd*3+kh)*3+kw;
                        const int off = (kd-1)*PLN + (kh-1)*DD + (kw-1);
                        bool v = v27[k];
                        float x0 = v ? b0[off]       : 0.0f;
                        float x1 = v ? b0[off + VOL] : 0.0f;
                        if (c2 == 1 && v) alive0v = fmaxf(alive0v, x1);   // ch3
                        u64t vp = pack2(x0, x1);
                        f0 = ffma2(vp, wp[k*3+0], f0);
                        f1 = ffma2(vp, wp[k*3+1], f1);
                        f2 = ffma2(vp, wp[k*3+2], f2);
                    }
            float lo, hi;
            unpack2(f0, lo, hi); buf[(c2*6+0)*BUFROW + t] = lo; buf[(c2*6+1)*BUFROW + t] = hi;
            unpack2(f1, lo, hi); buf[(c2*6+2)*BUFROW + t] = lo; buf[(c2*6+3)*BUFROW + t] = hi;
            unpack2(f2, lo, hi); buf[(c2*6+4)*BUFROW + t] = lo; buf[(c2*6+5)*BUFROW + t] = hi;
            b0 += 2*VOL;
        }
    }
    g_alive0[pos] = alive0v;
    __syncthreads();

    // ---- GEMM tiling: thread = 8 outputs x 8 voxels ----
    const int og = t / 24;        // 0..7
    const int vg = t % 24;        // 0..23
    const int o0 = og * 8;
    const int v0 = vg * 8;

    u64t acc[8][4];

    // ---- layer 1: 48 -> 64, tanh ----
    #pragma unroll
    for (int o = 0; o < 8; o++) {
        float b = s_b1[o0 + o]; u64t bb = pack2(b, b);
        #pragma unroll
        for (int q = 0; q < 4; q++) acc[o][q] = bb;
    }
    #pragma unroll 4
    for (int k = 0; k < 48; k++) {
        const float* wr = &s_w1t[k*64 + o0];
        float4 wA = *reinterpret_cast<const float4*>(wr);
        float4 wB = *reinterpret_cast<const float4*>(wr + 4);
        const float* ar = &buf[k*BUFROW + v0];
        ulonglong2 aA = *reinterpret_cast<const ulonglong2*>(ar);
        ulonglong2 aB = *reinterpret_cast<const ulonglong2*>(ar + 4);
        u64t a0 = aA.x, a1 = aA.y, a2 = aB.x, a3 = aB.y;
        float wv[8] = {wA.x, wA.y, wA.z, wA.w, wB.x, wB.y, wB.z, wB.w};
        #pragma unroll
        for (int o = 0; o < 8; o++) {
            u64t ww = pack2(wv[o], wv[o]);
            acc[o][0] = ffma2(ww, a0, acc[o][0]);
            acc[o][1] = ffma2(ww, a1, acc[o][1]);
            acc[o][2] = ffma2(ww, a2, acc[o][2]);
            acc[o][3] = ffma2(ww, a3, acc[o][3]);
        }
    }
    __syncthreads();
    #pragma unroll
    for (int o = 0; o < 8; o++)
        #pragma unroll
        for (int q = 0; q < 4; q++) {
            float lo, hi; unpack2(acc[o][q], lo, hi);
            *reinterpret_cast<u64t*>(&buf[(o0+o)*BUFROW + v0 + 2*q]) = pack2(tanh_fast(lo), tanh_fast(hi));
        }
    __syncthreads();

    // ---- layer 2: 64 -> 64, tanh ----
    #pragma unroll
    for (int o = 0; o < 8; o++) {
        float b = s_b2[o0 + o]; u64t bb = pack2(b, b);
        #pragma unroll
        for (int q = 0; q < 4; q++) acc[o][q] = bb;
    }
    #pragma unroll 4
    for (int k = 0; k < 64; k++) {
        const float* wr = &s_w2t[k*64 + o0];
        float4 wA = *reinterpret_cast<const float4*>(wr);
        float4 wB = *reinterpret_cast<const float4*>(wr + 4);
        const float* ar = &buf[k*BUFROW + v0];
        ulonglong2 aA = *reinterpret_cast<const ulonglong2*>(ar);
        ulonglong2 aB = *reinterpret_cast<const ulonglong2*>(ar + 4);
        u64t a0 = aA.x, a1 = aA.y, a2 = aB.x, a3 = aB.y;
        float wv[8] = {wA.x, wA.y, wA.z, wA.w, wB.x, wB.y, wB.z, wB.w};
        #pragma unroll
        for (int o = 0; o < 8; o++) {
            u64t ww = pack2(wv[o], wv[o]);
            acc[o][0] = ffma2(ww, a0, acc[o][0]);
            acc[o][1] = ffma2(ww, a1, acc[o][1]);
            acc[o][2] = ffma2(ww, a2, acc[o][2]);
            acc[o][3] = ffma2(ww, a3, acc[o][3]);
        }
    }
    __syncthreads();
    #pragma unroll
    for (int o = 0; o < 8; o++)
        #pragma unroll
        for (int q = 0; q < 4; q++) {
            float lo, hi; unpack2(acc[o][q], lo, hi);
            *reinterpret_cast<u64t*>(&buf[(o0+o)*BUFROW + v0 + 2*q]) = pack2(tanh_fast(lo), tanh_fast(hi));
        }
    __syncthreads();

    // ---- layer 3: 64 -> 16 (thread = 2 outputs x 8 voxels) ----
    const int o3 = og * 2;   // 0,2,..,14
    u64t acc3[2][4];
    #pragma unroll
    for (int cc = 0; cc < 2; cc++) {
        float b = s_b3[o3 + cc]; u64t bb = pack2(b, b);
        #pragma unroll
        for (int q = 0; q < 4; q++) acc3[cc][q] = bb;
    }
    #pragma unroll 4
    for (int k = 0; k < 64; k++) {
        float2 wv = *reinterpret_cast<const float2*>(&s_w3t[k*16 + o3]);
        const float* ar = &buf[k*BUFROW + v0];
        ulonglong2 aA = *reinterpret_cast<const ulonglong2*>(ar);
        ulonglong2 aB = *reinterpret_cast<const ulonglong2*>(ar + 4);
        u64t a0 = aA.x, a1 = aA.y, a2 = aB.x, a3 = aB.y;
        u64t w0 = pack2(wv.x, wv.x), w1v = pack2(wv.y, wv.y);
        acc3[0][0] = ffma2(w0, a0, acc3[0][0]);  acc3[0][1] = ffma2(w0, a1, acc3[0][1]);
        acc3[0][2] = ffma2(w0, a2, acc3[0][2]);  acc3[0][3] = ffma2(w0, a3, acc3[0][3]);
        acc3[1][0] = ffma2(w1v, a0, acc3[1][0]); acc3[1][1] = ffma2(w1v, a1, acc3[1][1]);
        acc3[1][2] = ffma2(w1v, a2, acc3[1][2]); acc3[1][3] = ffma2(w1v, a3, acc3[1][3]);
    }

    // ---- residual + store (coalesced, packed) ----
    float m3 = -INFINITY;
    #pragma unroll
    for (int cc = 0; cc < 2; cc++) {
        const int c = o3 + cc;
        const float* xr = cur + c*VOL + lin0 + v0;
        float* br = g_B + c*VOL + lin0 + v0;
        ulonglong2 xA = *reinterpret_cast<const ulonglong2*>(xr);
        ulonglong2 xB = *reinterpret_cast<const ulonglong2*>(xr + 4);
        ulonglong2 rA, rB;
        rA.x = fadd2(acc3[cc][0], xA.x); rA.y = fadd2(acc3[cc][1], xA.y);
        rB.x = fadd2(acc3[cc][2], xB.x); rB.y = fadd2(acc3[cc][3], xB.y);
        *reinterpret_cast<ulonglong2*>(br)     = rA;
        *reinterpret_cast<ulonglong2*>(br + 4) = rB;
        if (c == 3) {
            float lo, hi;
            unpack2(rA.x, lo, hi); m3 = fmaxf(m3, fmaxf(lo, hi));
            unpack2(rA.y, lo, hi); m3 = fmaxf(m3, fmaxf(lo, hi));
            unpack2(rB.x, lo, hi); m3 = fmaxf(m3, fmaxf(lo, hi));
            unpack2(rB.y, lo, hi); m3 = fmaxf(m3, fmaxf(lo, hi));
        }
    }
    if (og == 1) s_red[vg] = m3;   // og==1 holds channels 2,3
    __syncthreads();
    if (t == 0) {
        float mm = s_red[0];
        #pragma unroll
        for (int i = 1; i < 24; i++) mm = fmaxf(mm, s_red[i]);
        atomicMax(&g_maxPost[step], encf(mm));
    }
}

__global__ __launch_bounds__(96) void finalize_kernel(
    float* __restrict__ out, int step, const int* __restrict__ pInOut)
{
    float* dst = (step == 3) ? out : (float*)g_A;

    int w = threadIdx.x, h = blockIdx.x, d = blockIdx.y;
    int pos = d*PLN + h*DD + w;

    bool vD[3] = { d > 0, true, d < DD-1 };
    bool vH[3] = { h > 0, true, h < DD-1 };
    bool vW[3] = { w > 0, true, w < DD-1 };
    const float* B3 = g_B + 3*VOL + pos;
    float m1 = -INFINITY;
    #pragma unroll
    for (int kd = 0; kd < 3; kd++)
        #pragma unroll
        for (int kh = 0; kh < 3; kh++)
            #pragma unroll
            for (int kw = 0; kw < 3; kw++)
                if (vD[kd] && vH[kh] && vW[kw])
                    m1 = fmaxf(m1, B3[(kd-1)*PLN + (kh-1)*DD + (kw-1)]);

    float th0 = 0.1f * decf(g_maxPre[step]);  if (isnan(th0)) th0 = -INFINITY;
    float th1 = 0.1f * decf(g_maxPost[step]); if (isnan(th1)) th1 = -INFINITY;
    bool life = (g_alive0[pos] > th0) && (m1 > th1);
    float lf = life ? 1.0f : 0.0f;
    bool zero = (d == DD-1) && (h >= *pInOut);

    float v3 = 0.0f;
    #pragma unroll
    for (int c = 0; c < NC; c++) {
        float v = g_B[c*VOL + pos] * lf;
        if (zero) v = 0.0f;
        dst[c*VOL + pos] = v;
        if (c == 3) v3 = v;
    }

    float m = v3;
    #pragma unroll
    for (int s = 16; s > 0; s >>= 1) m = fmaxf(m, __shfl_xor_sync(0xffffffffu, m, s));
    __shared__ float s_wmax[3];
    if ((threadIdx.x & 31) == 0) s_wmax[threadIdx.x >> 5] = m;
    __syncthreads();
    if (threadIdx.x == 0) {
        float mm = fmaxf(fmaxf(s_wmax[0], s_wmax[1]), s_wmax[2]);
        atomicMax(&g_maxPre[step + 1], encf(mm));
    }
}

extern "C" void kernel_launch(void* const* d_in, const int* in_sizes, int n_in,
                              void* d_out, int out_size) {
    (void)in_sizes; (void)n_in; (void)out_size;
    const float* x      = (const float*)d_in[0];
    const float* w_perc = (const float*)d_in[1];
    const float* b_perc = (const float*)d_in[2];
    const float* w1     = (const float*)d_in[3];
    const float* b1     = (const float*)d_in[4];
    const float* w2     = (const float*)d_in[5];
    const float* b2     = (const float*)d_in[6];
    const float* w3     = (const float*)d_in[7];
    const float* b3     = (const float*)d_in[8];
    const int*   pInOut = (const int*)d_in[12];
    float* out = (float*)d_out;

    static bool attr_set = false;
    if (!attr_set) {
        cudaFuncSetAttribute(update_kernel, cudaFuncAttributeMaxDynamicSharedMemorySize, SMEM_BYTES);
        attr_set = true;
    }

    init_kernel<<<1, 32>>>();
    reduce_ch3_kernel<<<432, 256>>>(x + 3*VOL);

    dim3 fgrd(DD, DD);
    for (int s = 0; s < 4; s++) {
        update_kernel<<<4608, 192, SMEM_BYTES>>>(x, w_perc, b_perc, w1, b1, w2, b2, w3, b3, s);
        finalize_kernel<<<fgrd, 96>>>(out, s, pInOut);
    }
}

// round 6
// speedup vs baseline: 1.6725x; 1.6725x over previous
#include <cuda_runtime.h>
#include <math.h>
#include <stdint.h>

#define DD  96
#define PLN (DD*DD)
#define VOL (DD*DD*DD)
#define NC  16
#define SSTR 70           // activation buffer row stride (floats)

__device__ __align__(16) float g_A[NC*VOL];
__device__ __align__(16) float g_B[NC*VOL];
__device__ float    g_alive0[VOL];
__device__ unsigned g_maxPre[5];
__device__ unsigned g_maxPost[4];
__device__ unsigned long long g_Wpc[648];   // conv weight pairs
__device__ unsigned long long g_Bpp[24];    // conv bias pairs

__device__ __forceinline__ unsigned encf(float f) {
    unsigned u = __float_as_uint(f);
    return (u & 0x80000000u) ? ~u : (u | 0x80000000u);
}
__device__ __forceinline__ float decf(unsigned e) {
    return __uint_as_float((e & 0x80000000u) ? (e ^ 0x80000000u) : ~e);
}
__device__ __forceinline__ float tanh_fast(float x) {
    float y; asm("tanh.approx.f32 %0, %1;" : "=f"(y) : "f"(x)); return y;
}
typedef unsigned long long u64t;
__device__ __forceinline__ u64t pack2(float lo, float hi) {
    u64t r; asm("mov.b64 %0, {%1, %2};" : "=l"(r) : "f"(lo), "f"(hi)); return r;
}
__device__ __forceinline__ void unpack2(u64t v, float& lo, float& hi) {
    asm("mov.b64 {%0, %1}, %2;" : "=f"(lo), "=f"(hi) : "l"(v));
}
__device__ __forceinline__ u64t ffma2(u64t a, u64t b, u64t c) {
    u64t d; asm("fma.rn.f32x2 %0, %1, %2, %3;" : "=l"(d) : "l"(a), "l"(b), "l"(c)); return d;
}

// ---- 3xTF32 helpers ----
__device__ __forceinline__ void split_tf32(float a, uint32_t& hi, uint32_t& lo) {
    uint32_t ua = __float_as_uint(a);
    hi = ua & 0xFFFFE000u;                       // truncate: residual is exact in fp32
    float l = a - __uint_as_float(hi);
    lo = __float_as_uint(l) & 0xFFFFE000u;
}
__device__ __forceinline__ void mma_tf32(float* c, const uint32_t* a, uint32_t b0, uint32_t b1) {
    asm volatile("mma.sync.aligned.m16n8k8.row.col.f32.tf32.tf32.f32 "
        "{%0,%1,%2,%3}, {%4,%5,%6,%7}, {%8,%9}, {%0,%1,%2,%3};"
        : "+f"(c[0]), "+f"(c[1]), "+f"(c[2]), "+f"(c[3])
        : "r"(a[0]), "r"(a[1]), "r"(a[2]), "r"(a[3]), "r"(b0), "r"(b1));
}

// Generic MMA layer: D[128, NT*8] = S[128, KT*8] x Wg[NT*8, KT*8]^T (3xTF32)
template<int KT, int NT>
__device__ __forceinline__ void mma_layer(const float* S, const float* __restrict__ Wg,
                                          int wr0, int g, int q, float C[2][NT][4])
{
    #pragma unroll
    for (int m = 0; m < 2; m++)
        #pragma unroll
        for (int n = 0; n < NT; n++)
            #pragma unroll
            for (int i = 0; i < 4; i++) C[m][n][i] = 0.0f;

    #pragma unroll
    for (int k = 0; k < KT; k++) {
        uint32_t ah[2][4], al[2][4];
        #pragma unroll
        for (int m = 0; m < 2; m++) {
            int r = wr0 + m*16 + g;
            float a0 = S[r*SSTR + k*8 + q];
            float a1 = S[(r+8)*SSTR + k*8 + q];
            float a2 = S[r*SSTR + k*8 + q + 4];
            float a3 = S[(r+8)*SSTR + k*8 + q + 4];
            split_tf32(a0, ah[m][0], al[m][0]);
            split_tf32(a1, ah[m][1], al[m][1]);
            split_tf32(a2, ah[m][2], al[m][2]);
            split_tf32(a3, ah[m][3], al[m][3]);
        }
        #pragma unroll
        for (int n = 0; n < NT; n++) {
            float b0f = __ldg(&Wg[(n*8 + g)*(KT*8) + k*8 + q]);
            float b1f = __ldg(&Wg[(n*8 + g)*(KT*8) + k*8 + q + 4]);
            uint32_t bh0, bl0, bh1, bl1;
            split_tf32(b0f, bh0, bl0);
            split_tf32(b1f, bh1, bl1);
            #pragma unroll
            for (int m = 0; m < 2; m++) {
                mma_tf32(C[m][n], ah[m], bh0, bh1);
                mma_tf32(C[m][n], al[m], bh0, bh1);
                mma_tf32(C[m][n], ah[m], bl0, bl1);
            }
        }
    }
}

__global__ void init_kernel() {
    int t = threadIdx.x;
    if (t < 5) g_maxPre[t]  = 0x007FFFFFu;
    if (t < 4) g_maxPost[t] = 0x007FFFFFu;
}

__global__ void prep_weights(const float* __restrict__ w_perc, const float* __restrict__ b_perc) {
    int t = threadIdx.x;
    for (int idx = t; idx < 648; idx += 256) {
        int c2 = idx / 81, r = idx % 81, k = r / 3, j = r % 3;
        g_Wpc[idx] = pack2(w_perc[((2*c2)*3 + j)*27 + k], w_perc[((2*c2+1)*3 + j)*27 + k]);
    }
    if (t < 24) {
        int c2 = t / 3, j = t % 3;
        g_Bpp[t] = pack2(b_perc[(2*c2)*3 + j], b_perc[(2*c2+1)*3 + j]);
    }
}

__global__ void reduce_ch3_kernel(const float* __restrict__ p) {
    float m = -INFINITY;
    for (int i = blockIdx.x * blockDim.x + threadIdx.x; i < VOL; i += gridDim.x * blockDim.x)
        m = fmaxf(m, p[i]);
    #pragma unroll
    for (int s = 16; s > 0; s >>= 1) m = fmaxf(m, __shfl_xor_sync(0xffffffffu, m, s));
    __shared__ float sm[8];
    if ((threadIdx.x & 31) == 0) sm[threadIdx.x >> 5] = m;
    __syncthreads();
    if (threadIdx.x == 0) {
        int nw = (blockDim.x + 31) / 32;
        float mm = sm[0];
        for (int i = 1; i < nw; i++) mm = fmaxf(mm, sm[i]);
        atomicMax(&g_maxPre[0], encf(mm));
    }
}

// Conv (scalar FFMA2) + MLP (mma.sync tf32 3x). One 128-voxel tile per block.
__global__ __launch_bounds__(128, 4) void update_kernel(
    const float* __restrict__ xin,
    const float* __restrict__ w1, const float* __restrict__ b1,
    const float* __restrict__ w2, const float* __restrict__ b2,
    const float* __restrict__ w3, const float* __restrict__ b3,
    int step)
{
    const float* cur = (step == 0) ? xin : (const float*)g_A;

    __shared__ float S[128*SSTR];
    __shared__ u64t  s_wpc[648];
    __shared__ u64t  s_bpp[24];
    __shared__ float sb1[64], sb2[64], sb3[16];

    const int t = threadIdx.x;
    for (int i = t; i < 648; i += 128) s_wpc[i] = g_Wpc[i];
    if (t < 24) s_bpp[t] = g_Bpp[t];
    if (t < 64) { sb1[t] = b1[t]; sb2[t] = b2[t]; }
    if (t < 16) sb3[t] = b3[t];
    __syncthreads();

    const int tile = blockIdx.x;
    const int pos = tile*128 + t;
    const int w  = pos % DD;
    const int hh = (pos / DD) % DD;
    const int d  = pos / PLN;

    bool vD[3] = { d > 0, true, d < DD-1 };
    bool vH[3] = { hh > 0, true, hh < DD-1 };
    bool vW[3] = { w > 0, true, w < DD-1 };
    bool v27[27];
    #pragma unroll
    for (int kd = 0; kd < 3; kd++)
        #pragma unroll
        for (int kh = 0; kh < 3; kh++)
            #pragma unroll
            for (int kw = 0; kw < 3; kw++)
                v27[(kd*3+kh)*3+kw] = vD[kd] && vH[kh] && vW[kw];

    // ---- depthwise conv -> S[row t][cols 0..47] ----
    float alive0v = -INFINITY;
    {
        const float* bp = cur + pos;
        #pragma unroll 2
        for (int c2 = 0; c2 < 8; c2++) {
            u64t f0 = s_bpp[c2*3+0], f1 = s_bpp[c2*3+1], f2 = s_bpp[c2*3+2];
            const u64t* wp = &s_wpc[c2*81];
            #pragma unroll
            for (int kd = 0; kd < 3; kd++)
                #pragma unroll
                for (int kh = 0; kh < 3; kh++)
                    #pragma unroll
                    for (int kw = 0; kw < 3; kw++) {
                        const int k = (kd*3+kh)*3+kw;
                        const int off = (kd-1)*PLN + (kh-1)*DD + (kw-1);
                        bool v = v27[k];
                        float x0 = v ? bp[off]       : 0.0f;
                        float x1 = v ? bp[off + VOL] : 0.0f;
                        if (c2 == 1 && v) alive0v = fmaxf(alive0v, x1);   // ch3
                        u64t vp = pack2(x0, x1);
                        f0 = ffma2(vp, wp[k*3+0], f0);
                        f1 = ffma2(vp, wp[k*3+1], f1);
                        f2 = ffma2(vp, wp[k*3+2], f2);
                    }
            float lo, hi;
            unpack2(f0, lo, hi); S[t*SSTR + (2*c2)*3 + 0] = lo; S[t*SSTR + (2*c2+1)*3 + 0] = hi;
            unpack2(f1, lo, hi); S[t*SSTR + (2*c2)*3 + 1] = lo; S[t*SSTR + (2*c2+1)*3 + 1] = hi;
            unpack2(f2, lo, hi); S[t*SSTR + (2*c2)*3 + 2] = lo; S[t*SSTR + (2*c2+1)*3 + 2] = hi;
            bp += 2*VOL;
        }
    }
    g_alive0[pos] = alive0v;
    __syncthreads();

    const int wid = t >> 5, lane = t & 31;
    const int g = lane >> 2, q = lane & 3;
    const int wr0 = wid * 32;

    // ---- layer 1: 48 -> 64, tanh ----
    {
        float C[2][8][4];
        mma_layer<6, 8>(S, w1, wr0, g, q, C);
        __syncthreads();
        #pragma unroll
        for (int m = 0; m < 2; m++) {
            int r = wr0 + m*16 + g;
            #pragma unroll
            for (int n = 0; n < 8; n++) {
                int c0 = n*8 + 2*q;
                S[r*SSTR + c0]       = tanh_fast(C[m][n][0] + sb1[c0]);
                S[r*SSTR + c0+1]     = tanh_fast(C[m][n][1] + sb1[c0+1]);
                S[(r+8)*SSTR + c0]   = tanh_fast(C[m][n][2] + sb1[c0]);
                S[(r+8)*SSTR + c0+1] = tanh_fast(C[m][n][3] + sb1[c0+1]);
            }
        }
        __syncthreads();
    }

    // ---- layer 2: 64 -> 64, tanh ----
    {
        float C[2][8][4];
        mma_layer<8, 8>(S, w2, wr0, g, q, C);
        __syncthreads();
        #pragma unroll
        for (int m = 0; m < 2; m++) {
            int r = wr0 + m*16 + g;
            #pragma unroll
            for (int n = 0; n < 8; n++) {
                int c0 = n*8 + 2*q;
                S[r*SSTR + c0]       = tanh_fast(C[m][n][0] + sb2[c0]);
                S[r*SSTR + c0+1]     = tanh_fast(C[m][n][1] + sb2[c0+1]);
                S[(r+8)*SSTR + c0]   = tanh_fast(C[m][n][2] + sb2[c0]);
                S[(r+8)*SSTR + c0+1] = tanh_fast(C[m][n][3] + sb2[c0+1]);
            }
        }
        __syncthreads();
    }

    // ---- layer 3: 64 -> 16, residual + store ----
    {
        float C[2][2][4];
        mma_layer<8, 2>(S, w3, wr0, g, q, C);
        float m3 = -INFINITY;
        #pragma unroll
        for (int m = 0; m < 2; m++) {
            int r = wr0 + m*16 + g;
            int p0 = tile*128 + r, p1 = p0 + 8;
            #pragma unroll
            for (int n = 0; n < 2; n++) {
                int c0 = n*8 + 2*q, c1 = c0 + 1;
                float v00 = C[m][n][0] + sb3[c0] + cur[c0*VOL + p0];
                float v01 = C[m][n][1] + sb3[c1] + cur[c1*VOL + p0];
                float v10 = C[m][n][2] + sb3[c0] + cur[c0*VOL + p1];
                float v11 = C[m][n][3] + sb3[c1] + cur[c1*VOL + p1];
                g_B[c0*VOL + p0] = v00;
                g_B[c1*VOL + p0] = v01;
                g_B[c0*VOL + p1] = v10;
                g_B[c1*VOL + p1] = v11;
                if (c1 == 3) m3 = fmaxf(m3, fmaxf(v01, v11));
            }
        }
        #pragma unroll
        for (int s = 16; s > 0; s >>= 1) m3 = fmaxf(m3, __shfl_xor_sync(0xffffffffu, m3, s));
        if (lane == 0) atomicMax(&g_maxPost[step], encf(m3));
    }
}

__global__ __launch_bounds__(96) void finalize_kernel(
    float* __restrict__ out, int step, const int* __restrict__ pInOut)
{
    float* dst = (step == 3) ? out : (float*)g_A;

    int w = threadIdx.x, h = blockIdx.x, d = blockIdx.y;
    int pos = d*PLN + h*DD + w;

    bool vD[3] = { d > 0, true, d < DD-1 };
    bool vH[3] = { h > 0, true, h < DD-1 };
    bool vW[3] = { w > 0, true, w < DD-1 };
    const float* B3 = g_B + 3*VOL + pos;
    float m1 = -INFINITY;
    #pragma unroll
    for (int kd = 0; kd < 3; kd++)
        #pragma unroll
        for (int kh = 0; kh < 3; kh++)
            #pragma unroll
            for (int kw = 0; kw < 3; kw++)
                if (vD[kd] && vH[kh] && vW[kw])
                    m1 = fmaxf(m1, B3[(kd-1)*PLN + (kh-1)*DD + (kw-1)]);

    float th0 = 0.1f * decf(g_maxPre[step]);  if (isnan(th0)) th0 = -INFINITY;
    float th1 = 0.1f * decf(g_maxPost[step]); if (isnan(th1)) th1 = -INFINITY;
    bool life = (g_alive0[pos] > th0) && (m1 > th1);
    float lf = life ? 1.0f : 0.0f;
    bool zero = (d == DD-1) && (h >= *pInOut);

    float v3 = 0.0f;
    #pragma unroll
    for (int c = 0; c < NC; c++) {
        float v = g_B[c*VOL + pos] * lf;
        if (zero) v = 0.0f;
        dst[c*VOL + pos] = v;
        if (c == 3) v3 = v;
    }

    float m = v3;
    #pragma unroll
    for (int s = 16; s > 0; s >>= 1) m = fmaxf(m, __shfl_xor_sync(0xffffffffu, m, s));
    __shared__ float s_wmax[3];
    if ((threadIdx.x & 31) == 0) s_wmax[threadIdx.x >> 5] = m;
    __syncthreads();
    if (threadIdx.x == 0) {
        float mm = fmaxf(fmaxf(s_wmax[0], s_wmax[1]), s_wmax[2]);
        atomicMax(&g_maxPre[step + 1], encf(mm));
    }
}

extern "C" void kernel_launch(void* const* d_in, const int* in_sizes, int n_in,
                              void* d_out, int out_size) {
    (void)in_sizes; (void)n_in; (void)out_size;
    const float* x      = (const float*)d_in[0];
    const float* w_perc = (const float*)d_in[1];
    const float* b_perc = (const float*)d_in[2];
    const float* w1     = (const float*)d_in[3];
    const float* b1     = (const float*)d_in[4];
    const float* w2     = (const float*)d_in[5];
    const float* b2     = (const float*)d_in[6];
    const float* w3     = (const float*)d_in[7];
    const float* b3     = (const float*)d_in[8];
    const int*   pInOut = (const int*)d_in[12];
    float* out = (float*)d_out;

    init_kernel<<<1, 32>>>();
    prep_weights<<<1, 256>>>(w_perc, b_perc);
    reduce_ch3_kernel<<<432, 256>>>(x + 3*VOL);

    dim3 fgrd(DD, DD);
    for (int s = 0; s < 4; s++) {
        update_kernel<<<VOL/128, 128>>>(x, w1, b1, w2, b2, w3, b3, s);
        finalize_kernel<<<fgrd, 96>>>(out, s, pInOut);
    }
}

// round 7
// speedup vs baseline: 1.7698x; 1.0582x over previous
#include <cuda_runtime.h>
#include <math.h>
#include <stdint.h>

#define DD  96
#define PLN (DD*DD)
#define VOL (DD*DD*DD)
#define NC  16
#define SSTR 68                   // S row stride (floats): 272B, 16B-aligned
#define SMEM_BYTES (192*SSTR*4)   // 52224

__device__ __align__(16) float g_A[NC*VOL];
__device__ __align__(16) float g_B[NC*VOL];
__device__ float    g_alive0[VOL];
__device__ unsigned g_maxPre[5];
__device__ unsigned g_maxPost[4];

typedef unsigned long long u64t;
__device__ __align__(16) u64t  g_Wq[8*9*12];        // conv weight pairs, padded [c2][dh][12]
__device__ u64t  g_Bpp[24];                          // conv bias pairs
__device__ __align__(16) uint4 g_Wf1[6*8*32];        // layer1 fragments (K perm applied)
__device__ __align__(16) uint4 g_Wf2[8*8*32];
__device__ __align__(16) uint4 g_Wf3[8*2*32];

__device__ __forceinline__ unsigned encf(float f) {
    unsigned u = __float_as_uint(f);
    return (u & 0x80000000u) ? ~u : (u | 0x80000000u);
}
__device__ __forceinline__ float decf(unsigned e) {
    return __uint_as_float((e & 0x80000000u) ? (e ^ 0x80000000u) : ~e);
}
__device__ __forceinline__ float tanh_fast(float x) {
    float y; asm("tanh.approx.f32 %0, %1;" : "=f"(y) : "f"(x)); return y;
}
__device__ __forceinline__ u64t pack2(float lo, float hi) {
    u64t r; asm("mov.b64 %0, {%1, %2};" : "=l"(r) : "f"(lo), "f"(hi)); return r;
}
__device__ __forceinline__ u64t ffma2(u64t a, u64t b, u64t c) {
    u64t d; asm("fma.rn.f32x2 %0, %1, %2, %3;" : "=l"(d) : "l"(a), "l"(b), "l"(c)); return d;
}
__device__ __host__ __forceinline__ void split_tf32_h(float a, uint32_t& hi, uint32_t& lo) {
    uint32_t ua;
#ifdef __CUDA_ARCH__
    ua = __float_as_uint(a);
#else
    ua = *(uint32_t*)&a;
#endif
    hi = ua & 0xFFFFE000u;
    float hf;
#ifdef __CUDA_ARCH__
    hf = __uint_as_float(hi);
#else
    hf = *(float*)&hi;
#endif
    float l = a - hf;
#ifdef __CUDA_ARCH__
    lo = __float_as_uint(l) & 0xFFFFE000u;
#else
    lo = (*(uint32_t*)&l) & 0xFFFFE000u;
#endif
}
__device__ __forceinline__ void split_tf32(float a, uint32_t& hi, uint32_t& lo) {
    uint32_t ua = __float_as_uint(a);
    hi = ua & 0xFFFFE000u;
    float l = a - __uint_as_float(hi);
    lo = __float_as_uint(l) & 0xFFFFE000u;
}
__device__ __forceinline__ void mma_tf32(float* c, const uint32_t* a, uint32_t b0, uint32_t b1) {
    asm volatile("mma.sync.aligned.m16n8k8.row.col.f32.tf32.tf32.f32 "
        "{%0,%1,%2,%3}, {%4,%5,%6,%7}, {%8,%9}, {%0,%1,%2,%3};"
        : "+f"(c[0]), "+f"(c[1]), "+f"(c[2]), "+f"(c[3])
        : "r"(a[0]), "r"(a[1]), "r"(a[2]), "r"(a[3]), "r"(b0), "r"(b1));
}
__device__ __forceinline__ void ldm_x4(uint32_t addr, uint32_t* r) {
    asm volatile("ldmatrix.sync.aligned.m8n8.x4.shared.b16 {%0,%1,%2,%3}, [%4];"
        : "=r"(r[0]), "=r"(r[1]), "=r"(r[2]), "=r"(r[3]) : "r"(addr));
}
__device__ __forceinline__ uint32_t smem_u32(const void* p) {
    uint32_t a; asm("{ .reg .u64 t; cvta.to.shared.u64 t, %1; cvt.u32.u64 %0, t; }" : "=r"(a) : "l"(p));
    return a;
}

// S column s <- conv output (channel c=2*c2+b, dup j): s = 6*c2 + 2*j + b. Inverse:
__device__ __forceinline__ int inv_perm(int s) {
    int c2 = s / 6, r = s % 6, j = r >> 1, b = r & 1;
    return (2*c2 + b)*3 + j;
}

__global__ void init_kernel() {
    int t = threadIdx.x;
    if (t < 5) g_maxPre[t]  = 0x007FFFFFu;
    if (t < 4) g_maxPost[t] = 0x007FFFFFu;
}

__global__ void prep_weights(const float* __restrict__ w_perc, const float* __restrict__ b_perc,
                             const float* __restrict__ w1, const float* __restrict__ w2,
                             const float* __restrict__ w3) {
    int t = threadIdx.x;
    // conv weights: [(c2*9+dh)*12 + kw*3 + j]
    for (int idx = t; idx < 8*9*9; idx += 256) {
        int c2 = idx / 81, r = idx % 81, dh = r / 9, kk = r % 9, kw = kk / 3, j = kk % 3;
        int kf = dh*3 + kw;
        g_Wq[(c2*9 + dh)*12 + kw*3 + j] =
            pack2(w_perc[((2*c2)*3 + j)*27 + kf], w_perc[((2*c2+1)*3 + j)*27 + kf]);
    }
    if (t < 24) {
        int c2 = t / 3, j = t % 3;
        g_Bpp[t] = pack2(b_perc[(2*c2)*3 + j], b_perc[(2*c2+1)*3 + j]);
    }
    // layer1 fragments with K-permutation
    for (int idx = t; idx < 6*8*32; idx += 256) {
        int k = idx / 256, n = (idx / 32) % 8, l = idx % 32;
        int g = l >> 2, q = l & 3, ro = n*8 + g;
        float b0 = w1[ro*48 + inv_perm(8*k + q)];
        float b1 = w1[ro*48 + inv_perm(8*k + q + 4)];
        uint4 f; split_tf32_h(b0, f.x, f.z); split_tf32_h(b1, f.y, f.w);
        g_Wf1[idx] = f;
    }
    for (int idx = t; idx < 8*8*32; idx += 256) {
        int k = idx / 256, n = (idx / 32) % 8, l = idx % 32;
        int g = l >> 2, q = l & 3, ro = n*8 + g;
        float b0 = w2[ro*64 + 8*k + q];
        float b1 = w2[ro*64 + 8*k + q + 4];
        uint4 f; split_tf32_h(b0, f.x, f.z); split_tf32_h(b1, f.y, f.w);
        g_Wf2[idx] = f;
    }
    for (int idx = t; idx < 8*2*32; idx += 256) {
        int k = idx / 64, n = (idx / 32) % 2, l = idx % 32;
        int g = l >> 2, q = l & 3, ro = n*8 + g;
        float b0 = w3[ro*64 + 8*k + q];
        float b1 = w3[ro*64 + 8*k + q + 4];
        uint4 f; split_tf32_h(b0, f.x, f.z); split_tf32_h(b1, f.y, f.w);
        g_Wf3[idx] = f;
    }
}

__global__ void reduce_ch3_kernel(const float* __restrict__ p) {
    float m = -INFINITY;
    for (int i = blockIdx.x * blockDim.x + threadIdx.x; i < VOL; i += gridDim.x * blockDim.x)
        m = fmaxf(m, p[i]);
    #pragma unroll
    for (int s = 16; s > 0; s >>= 1) m = fmaxf(m, __shfl_xor_sync(0xffffffffu, m, s));
    __shared__ float sm[8];
    if ((threadIdx.x & 31) == 0) sm[threadIdx.x >> 5] = m;
    __syncthreads();
    if (threadIdx.x == 0) {
        int nw = (blockDim.x + 31) / 32;
        float mm = sm[0];
        for (int i = 1; i < nw; i++) mm = fmaxf(mm, sm[i]);
        atomicMax(&g_maxPre[0], encf(mm));
    }
}

// MMA pass: 32 rows (2 m-tiles) x NT*8 outputs over KT*8 K, 3xTF32.
template<int KT, int NT>
__device__ __forceinline__ void mma_pass(uint32_t aBase, const uint4* __restrict__ Wf,
                                         int lane, float C[2][NT][4])
{
    #pragma unroll
    for (int m = 0; m < 2; m++)
        #pragma unroll
        for (int n = 0; n < NT; n++)
            #pragma unroll
            for (int i = 0; i < 4; i++) C[m][n][i] = 0.0f;

    #pragma unroll
    for (int k = 0; k < KT; k++) {
        uint32_t a0[4], a1[4];
        ldm_x4(aBase + k*32, a0);
        ldm_x4(aBase + 16*SSTR*4 + k*32, a1);
        uint32_t ah0[4], al0[4], ah1[4], al1[4];
        #pragma unroll
        for (int i = 0; i < 4; i++) {
            split_tf32(__uint_as_float(a0[i]), ah0[i], al0[i]);
            split_tf32(__uint_as_float(a1[i]), ah1[i], al1[i]);
        }
        #pragma unroll
        for (int n = 0; n < NT; n++) {
            uint4 wf = Wf[(k*NT + n)*32 + lane];
            mma_tf32(C[0][n], ah0, wf.x, wf.y);
            mma_tf32(C[0][n], al0, wf.x, wf.y);
            mma_tf32(C[0][n], ah0, wf.z, wf.w);
            mma_tf32(C[1][n], ah1, wf.x, wf.y);
            mma_tf32(C[1][n], al1, wf.x, wf.y);
            mma_tf32(C[1][n], ah1, wf.z, wf.w);
        }
    }
}

// Update: block = 192 contiguous voxels (2 h-rows), 96 threads (2 voxels each), 3 warps.
__global__ __launch_bounds__(96, 4) void update_kernel(
    const float* __restrict__ xin,
    const float* __restrict__ b1, const float* __restrict__ b2, const float* __restrict__ b3,
    int step)
{
    const float* cur = (step == 0) ? xin : (const float*)g_A;

    extern __shared__ float S[];
    __shared__ float sb1[64], sb2[64], sb3[16];

    const int t = threadIdx.x;
    if (t < 64) { sb1[t] = b1[t]; sb2[t] = b2[t]; }
    if (t < 16) sb3[t] = b3[t];
    __syncthreads();

    const int bb = blockIdx.x * 192;          // block base voxel (linear)
    const int d  = blockIdx.x / 48;
    const int h0 = (blockIdx.x % 48) * 2;
    const int lv = 2*t;                        // local voxel of first of pair
    const int w0 = lv % 96;
    const int h  = h0 + lv / 96;
    const int p0 = bb + lv;

    const bool vD[3] = { d > 0, true, d < DD-1 };
    const bool vH[3] = { h > 0, true, h < DD-1 };
    const bool wl = (w0 > 0), wr = (w0 < 94);

    // ---- depthwise conv: 2 voxels/thread, channel-paired FFMA2 ----
    {
        float aA = -INFINITY, aB = -INFINITY;
        #pragma unroll 2
        for (int c2 = 0; c2 < 8; c2++) {
            u64t fA0 = g_Bpp[c2*3+0], fA1 = g_Bpp[c2*3+1], fA2 = g_Bpp[c2*3+2];
            u64t fB0 = fA0, fB1 = fA1, fB2 = fA2;
            const float* baseA = cur + (2*c2)*VOL;
            const float* baseB = baseA + VOL;
            #pragma unroll
            for (int kd = 0; kd < 3; kd++)
                #pragma unroll
                for (int kh = 0; kh < 3; kh++) {
                    if (vD[kd] && vH[kh]) {
                        const int nb = p0 + (kd-1)*PLN + (kh-1)*DD;
                        float2 ca = *reinterpret_cast<const float2*>(baseA + nb);
                        float2 cb = *reinterpret_cast<const float2*>(baseB + nb);
                        float ma = wl ? baseA[nb-1] : 0.0f;
                        float mb = wl ? baseB[nb-1] : 0.0f;
                        float pa = wr ? baseA[nb+2] : 0.0f;
                        float pb = wr ? baseB[nb+2] : 0.0f;
                        if (c2 == 1) {   // channel 3 is hi lane
                            float mx = fmaxf(cb.x, cb.y);
                            aA = fmaxf(aA, mx); if (wl) aA = fmaxf(aA, mb);
                            aB = fmaxf(aB, mx); if (wr) aB = fmaxf(aB, pb);
                        }
                        const ulonglong2* wp2 = reinterpret_cast<const ulonglong2*>(
                            g_Wq + (c2*9 + kd*3 + kh)*12);
                        ulonglong2 q0 = wp2[0], q1 = wp2[1], q2 = wp2[2], q3 = wp2[3];
                        u64t w8 = reinterpret_cast<const u64t*>(wp2)[8];
                        u64t Pm = pack2(ma, mb), Pc0 = pack2(ca.x, cb.x);
                        u64t Pc1 = pack2(ca.y, cb.y), Pp = pack2(pa, pb);
                        // voxA: kw0=Pm, kw1=Pc0, kw2=Pc1 ; voxB: kw0=Pc0, kw1=Pc1, kw2=Pp
                        fA0 = ffma2(Pm,  q0.x, fA0); fA1 = ffma2(Pm,  q0.y, fA1); fA2 = ffma2(Pm,  q1.x, fA2);
                        fA0 = ffma2(Pc0, q1.y, fA0); fA1 = ffma2(Pc0, q2.x, fA1); fA2 = ffma2(Pc0, q2.y, fA2);
                        fA0 = ffma2(Pc1, q3.x, fA0); fA1 = ffma2(Pc1, q3.y, fA1); fA2 = ffma2(Pc1, w8,   fA2);
                        fB0 = ffma2(Pc0, q0.x, fB0); fB1 = ffma2(Pc0, q0.y, fB1); fB2 = ffma2(Pc0, q1.x, fB2);
                        fB0 = ffma2(Pc1, q1.y, fB0); fB1 = ffma2(Pc1, q2.x, fB1); fB2 = ffma2(Pc1, q2.y, fB2);
                        fB0 = ffma2(Pp,  q3.x, fB0); fB1 = ffma2(Pp,  q3.y, fB1); fB2 = ffma2(Pp,  w8,   fB2);
                    }
                }
            // store column pairs: col = 6*c2 + 2*j (+b) == the u64 accumulator
            u64t* rowA = reinterpret_cast<u64t*>(&S[lv*SSTR + 6*c2]);
            u64t* rowB = reinterpret_cast<u64t*>(&S[(lv+1)*SSTR + 6*c2]);
            rowA[0] = fA0; rowA[1] = fA1; rowA[2] = fA2;
            rowB[0] = fB0; rowB[1] = fB1; rowB[2] = fB2;
        }
        *reinterpret_cast<float2*>(&g_alive0[p0]) = make_float2(aA, aB);
    }
    __syncwarp();

    const int wid = t >> 5, lane = t & 31;
    const int g = lane >> 2, q = lane & 3;
    const uint32_t sbase = smem_u32(S);
    float m3 = -INFINITY;

    // per-pass A base address for ldmatrix
    #define ABASE(base_r) (sbase + (((base_r) + (lane & 15))*SSTR + ((lane >> 4) << 2))*4)

    // ---- layer 1: 48 -> 64, tanh ----
    #pragma unroll
    for (int pass = 0; pass < 2; pass++) {
        const int base_r = wid*64 + pass*32;
        float C[2][8][4];
        mma_pass<6, 8>(ABASE(base_r), g_Wf1, lane, C);
        #pragma unroll
        for (int m = 0; m < 2; m++) {
            int rA = base_r + m*16 + g;
            #pragma unroll
            for (int n = 0; n < 8; n++) {
                int c0 = 8*n + 2*q;
                *reinterpret_cast<u64t*>(&S[rA*SSTR + c0]) =
                    pack2(tanh_fast(C[m][n][0] + sb1[c0]), tanh_fast(C[m][n][1] + sb1[c0+1]));
                *reinterpret_cast<u64t*>(&S[(rA+8)*SSTR + c0]) =
                    pack2(tanh_fast(C[m][n][2] + sb1[c0]), tanh_fast(C[m][n][3] + sb1[c0+1]));
            }
        }
        __syncwarp();
    }

    // ---- layer 2: 64 -> 64, tanh ----
    #pragma unroll
    for (int pass = 0; pass < 2; pass++) {
        const int base_r = wid*64 + pass*32;
        float C[2][8][4];
        mma_pass<8, 8>(ABASE(base_r), g_Wf2, lane, C);
        #pragma unroll
        for (int m = 0; m < 2; m++) {
            int rA = base_r + m*16 + g;
            #pragma unroll
            for (int n = 0; n < 8; n++) {
                int c0 = 8*n + 2*q;
                *reinterpret_cast<u64t*>(&S[rA*SSTR + c0]) =
                    pack2(tanh_fast(C[m][n][0] + sb2[c0]), tanh_fast(C[m][n][1] + sb2[c0+1]));
                *reinterpret_cast<u64t*>(&S[(rA+8)*SSTR + c0]) =
                    pack2(tanh_fast(C[m][n][2] + sb2[c0]), tanh_fast(C[m][n][3] + sb2[c0+1]));
            }
        }
        __syncwarp();
    }

    // ---- layer 3: 64 -> 16, residual + store ----
    #pragma unroll
    for (int pass = 0; pass < 2; pass++) {
        const int base_r = wid*64 + pass*32;
        float C[2][2][4];
        mma_pass<8, 2>(ABASE(base_r), g_Wf3, lane, C);
        #pragma unroll
        for (int m = 0; m < 2; m++) {
            int rA = base_r + m*16 + g;
            int pA = bb + rA, pB = pA + 8;
            #pragma unroll
            for (int n = 0; n < 2; n++) {
                int c0 = 8*n + 2*q, c1 = c0 + 1;
                float v00 = C[m][n][0] + sb3[c0] + cur[c0*VOL + pA];
                float v01 = C[m][n][1] + sb3[c1] + cur[c1*VOL + pA];
                float v10 = C[m][n][2] + sb3[c0] + cur[c0*VOL + pB];
                float v11 = C[m][n][3] + sb3[c1] + cur[c1*VOL + pB];
                g_B[c0*VOL + pA] = v00;
                g_B[c1*VOL + pA] = v01;
                g_B[c0*VOL + pB] = v10;
                g_B[c1*VOL + pB] = v11;
                if (c1 == 3) m3 = fmaxf(m3, fmaxf(v01, v11));
            }
        }
    }
    #pragma unroll
    for (int s = 16; s > 0; s >>= 1) m3 = fmaxf(m3, __shfl_xor_sync(0xffffffffu, m3, s));
    if (lane == 0) atomicMax(&g_maxPost[step], encf(m3));
    #undef ABASE
}

__global__ __launch_bounds__(96) void finalize_kernel(
    float* __restrict__ out, int step, const int* __restrict__ pInOut)
{
    float* dst = (step == 3) ? out : (float*)g_A;

    int w = threadIdx.x, h = blockIdx.x, d = blockIdx.y;
    int pos = d*PLN + h*DD + w;

    bool vD[3] = { d > 0, true, d < DD-1 };
    bool vH[3] = { h > 0, true, h < DD-1 };
    bool vW[3] = { w > 0, true, w < DD-1 };
    const float* B3 = g_B + 3*VOL + pos;
    float m1 = -INFINITY;
    #pragma unroll
    for (int kd = 0; kd < 3; kd++)
        #pragma unroll
        for (int kh = 0; kh < 3; kh++)
            #pragma unroll
            for (int kw = 0; kw < 3; kw++)
                if (vD[kd] && vH[kh] && vW[kw])
                    m1 = fmaxf(m1, B3[(kd-1)*PLN + (kh-1)*DD + (kw-1)]);

    float th0 = 0.1f * decf(g_maxPre[step]);  if (isnan(th0)) th0 = -INFINITY;
    float th1 = 0.1f * decf(g_maxPost[step]); if (isnan(th1)) th1 = -INFINITY;
    bool life = (g_alive0[pos] > th0) && (m1 > th1);
    float lf = life ? 1.0f : 0.0f;
    bool zero = (d == DD-1) && (h >= *pInOut);

    float v3 = 0.0f;
    #pragma unroll
    for (int c = 0; c < NC; c++) {
        float v = g_B[c*VOL + pos] * lf;
        if (zero) v = 0.0f;
        dst[c*VOL + pos] = v;
        if (c == 3) v3 = v;
    }

    float m = v3;
    #pragma unroll
    for (int s = 16; s > 0; s >>= 1) m = fmaxf(m, __shfl_xor_sync(0xffffffffu, m, s));
    __shared__ float s_wmax[3];
    if ((threadIdx.x & 31) == 0) s_wmax[threadIdx.x >> 5] = m;
    __syncthreads();
    if (threadIdx.x == 0) {
        float mm = fmaxf(fmaxf(s_wmax[0], s_wmax[1]), s_wmax[2]);
        atomicMax(&g_maxPre[step + 1], encf(mm));
    }
}

extern "C" void kernel_launch(void* const* d_in, const int* in_sizes, int n_in,
                              void* d_out, int out_size) {
    (void)in_sizes; (void)n_in; (void)out_size;
    const float* x      = (const float*)d_in[0];
    const float* w_perc = (const float*)d_in[1];
    const float* b_perc = (const float*)d_in[2];
    const float* w1     = (const float*)d_in[3];
    const float* b1     = (const float*)d_in[4];
    const float* w2     = (const float*)d_in[5];
    const float* b2     = (const float*)d_in[6];
    const float* w3     = (const float*)d_in[7];
    const float* b3     = (const float*)d_in[8];
    const int*   pInOut = (const int*)d_in[12];
    float* out = (float*)d_out;

    static bool attr_set = false;
    if (!attr_set) {
        cudaFuncSetAttribute(update_kernel, cudaFuncAttributeMaxDynamicSharedMemorySize, SMEM_BYTES);
        attr_set = true;
    }

    init_kernel<<<1, 32>>>();
    prep_weights<<<1, 256>>>(w_perc, b_perc, w1, w2, w3);
    reduce_ch3_kernel<<<432, 256>>>(x + 3*VOL);

    dim3 fgrd(DD, DD);
    for (int s = 0; s < 4; s++) {
        update_kernel<<<VOL/192, 96, SMEM_BYTES>>>(x, b1, b2, b3, s);
        finalize_kernel<<<fgrd, 96>>>(out, s, pInOut);
    }
}